// round 16
// baseline (speedup 1.0000x reference)
#include <cuda_runtime.h>
#include <cstdint>
#include <math.h>

#define EPS 1e-8f
#define RAD2DEG 57.295779513082320876798154814105f

#define THREADS    128
#define TILE_ROWS  128
#define QCOLS      4          // float4 per row per quarter-tile (16 floats)
#define SSTRIDE    16         // floats per row (no pad; XOR swizzle)
#define NBUF       3          // ring depth (>= prefetch distance 2 + 1)
#define CTAS_SM    9          // 9 x 24.84KB = 223.6KB <= 228KB smem/SM

// Inputs: data [N,64] f32, lab [N,3] f32, W [64,3] f32, b [3] f32 ; out [N] f32
//
// Best-measured structure (R15): column-quarter cp.async ring (distance 2,
// one block barrier per item), thread-per-row compute, dynamic work
// stealing, self-resetting counters, full-tile fast path.
// This round: occupancy 8 -> 9 CTAs/SM (smem just fits; launch_bounds caps
// regs at 56) to cover the latency gaps around the per-item barrier.

__device__ unsigned int g_tile_ctr = 0;   // tickets (tile = gridDim.x + k)
__device__ unsigned int g_done_ctr = 0;   // CTAs finished

__device__ __forceinline__ void cp_async16(unsigned int dst, const void* src) {
    asm volatile("cp.async.cg.shared.global [%0], [%1], 16;\n"
                 :: "r"(dst), "l"(src));
}
__device__ __forceinline__ void cp_commit() {
    asm volatile("cp.async.commit_group;\n");
}
template <int n>
__device__ __forceinline__ void cp_wait() {
    asm volatile("cp.async.wait_group %0;\n" :: "n"(n));
}

__global__ __launch_bounds__(THREADS, CTAS_SM) void cosine_loss_kernel(
    const float* __restrict__ data,
    const float* __restrict__ lab,
    const float* __restrict__ W,
    const float* __restrict__ b,
    float* __restrict__ out,
    int N, int ntiles)
{
    __shared__ __align__(16) float sbuf[NBUF][TILE_ROWS * SSTRIDE]; // 3 x 8KB
    __shared__ __align__(16) float sW[3][64];
    __shared__ float sb[3];
    __shared__ int s_next;

    const int t = threadIdx.x;
    const int nblk = (int)gridDim.x;

    if (t < 192) { int k = t / 3, c = t % 3; sW[c][k] = W[t]; }
    {
        int i = t + 128;
        if (i < 192) { int k = i / 3, c = i % 3; sW[c][k] = W[i]; }
    }
    if (t < 3) sb[t] = b[t];

    int tile_cur = blockIdx.x;
    if (t == 0) s_next = nblk + (int)atomicAdd(&g_tile_ctr, 1u);
    __syncthreads();                       // W/b staged + s_next visible
    int tile_next = s_next;

    // Stage quarter q of `tile` into sbuf[slot].
    auto prefetch = [&](int tile, int q, int slot) {
        if (tile >= ntiles) { cp_commit(); return; }
        int row0 = tile * TILE_ROWS;
        const float4* gsrc = reinterpret_cast<const float4*>(data);
        unsigned int sdst =
            (unsigned int)__cvta_generic_to_shared(&sbuf[slot][0]);
        if (row0 + TILE_ROWS <= N) {
            // FULL TILE: no per-load guard.
            #pragma unroll
            for (int j = 0; j < QCOLS; ++j) {
                int v = j * THREADS + t;
                int r = v >> 2;
                int c = v & 3;
                int cs = c ^ ((r >> 1) & 3);
                cp_async16(sdst + (unsigned int)((r * SSTRIDE + cs * 4) * 4),
                           &gsrc[(size_t)(row0 + r) * 16 + q * QCOLS + c]);
            }
        } else {
            #pragma unroll
            for (int j = 0; j < QCOLS; ++j) {
                int v = j * THREADS + t;
                int r = v >> 2;
                int c = v & 3;
                int cs = c ^ ((r >> 1) & 3);
                if (row0 + r < N)
                    cp_async16(sdst + (unsigned int)((r * SSTRIDE + cs * 4) * 4),
                               &gsrc[(size_t)(row0 + r) * 16 + q * QCOLS + c]);
            }
        }
        cp_commit();
    };

    // Prime pipeline (distance 2): quarters 0,1 of the first tile.
    prefetch(tile_cur, 0, 0);
    prefetch(tile_cur, 1, 1);

    const float4* __restrict__ w0v = reinterpret_cast<const float4*>(sW[0]);
    const float4* __restrict__ w1v = reinterpret_cast<const float4*>(sW[1]);
    const float4* __restrict__ w2v = reinterpret_cast<const float4*>(sW[2]);

    const int myswz = (t >> 1) & 3;

    float acc0 = 0.f, acc1 = 0.f, acc2 = 0.f;
    float l0 = 0.f, l1 = 0.f, l2 = 0.f;
    int item = 0;

    while (tile_cur < ntiles) {
        const int row  = tile_cur * TILE_ROWS + t;
        const bool live = (row < N);

        #pragma unroll
        for (int q = 0; q < 4; ++q, ++item) {
            cp_wait<1>();
            __syncthreads();   // buffer (item%NBUF) staged; prior reads done

            if (q == 0) {
                tile_next = s_next;            // stolen at prev tile's q==1
                acc0 = acc1 = acc2 = 0.f;
                if (live) {
                    const float* lr = lab + (size_t)row * 3;
                    l0 = __ldcs(&lr[0]); l1 = __ldcs(&lr[1]); l2 = __ldcs(&lr[2]);
                }
            }

            // Steal early (consumed at next q==0): ~3 items of slack over
            // the global-atomic latency.
            if (q == 1 && t == 0 && tile_next < ntiles)
                s_next = nblk + (int)atomicAdd(&g_tile_ctr, 1u);

            const float4* __restrict__ dv =
                reinterpret_cast<const float4*>(&sbuf[item % NBUF][t * SSTRIDE]);

            #pragma unroll
            for (int k = 0; k < QCOLS; ++k) {
                float4 d  = dv[k ^ myswz];
                int kk = q * QCOLS + k;
                float4 w0 = w0v[kk];
                float4 w1 = w1v[kk];
                float4 w2 = w2v[kk];
                acc0 += d.x * w0.x + d.y * w0.y + d.z * w0.z + d.w * w0.w;
                acc1 += d.x * w1.x + d.y * w1.y + d.z * w1.z + d.w * w1.w;
                acc2 += d.x * w2.x + d.y * w2.y + d.z * w2.z + d.w * w2.w;
            }

            if (q == 3 && live) {
                float p0 = acc0 + sb[0];
                float p1 = acc1 + sb[1];
                float p2 = acc2 + sb[2];

                float n = sqrtf(p0 * p0 + p1 * p1 + p2 * p2);
                float inv = 1.0f / fmaxf(n, EPS);
                float pn0 = p0 * inv, pn1 = p1 * inv, pn2 = p2 * inv;

                float dot = pn0 * l0 + pn1 * l1 + pn2 * l2;
                float na = fmaxf(sqrtf(pn0*pn0 + pn1*pn1 + pn2*pn2), EPS);
                float nb = fmaxf(sqrtf(l0*l0 + l1*l1 + l2*l2), EPS);
                float cosv = dot / (na * nb);

                float loss = acosf(cosv) * RAD2DEG;
                if (isnan(loss)) loss = 0.0f;
                __stcs(&out[row], loss);
            }

            // Prefetch item+2: quarter (q+2)&3 of tile_cur (q<2) or tile_next.
            int pq    = (q + 2) & 3;
            int ptile = (q < 2) ? tile_cur : tile_next;
            prefetch(ptile, pq, (item + 2) % NBUF);
        }

        tile_cur = tile_next;
    }

    // Last CTA resets counters for the next graph replay.
    if (t == 0) {
        __threadfence();
        unsigned int d = atomicAdd(&g_done_ctr, 1u);
        if (d == (unsigned int)nblk - 1u) {
            g_tile_ctr = 0u;
            g_done_ctr = 0u;
        }
    }
}

extern "C" void kernel_launch(void* const* d_in, const int* in_sizes, int n_in,
                              void* d_out, int out_size)
{
    const float* data = (const float*)d_in[0];
    const float* lab  = (const float*)d_in[1];
    const float* W    = (const float*)d_in[2];
    const float* b    = (const float*)d_in[3];
    float* out = (float*)d_out;

    int N = in_sizes[0] / 64;
    int ntiles = (N + TILE_ROWS - 1) / TILE_ROWS;
    int blocks = 148 * CTAS_SM;
    if (blocks > ntiles) blocks = ntiles;

    cosine_loss_kernel<<<blocks, THREADS>>>(data, lab, W, b, out, N, ntiles);
}